// round 1
// baseline (speedup 1.0000x reference)
#include <cuda_runtime.h>
#include <cstdint>

// Problem dims
#define MB   16384   // batch
#define K1   2048    // IN_DIM
#define N1   8192    // HV_DIM
#define NC   1000    // NUM_CLASSES
#define KW   256     // N1/32 packed words per row

// Scratch (allocation-free rule: __device__ globals)
__device__ unsigned g_rbits[(size_t)MB * KW];    // packed sign bits of hv_bin, [row][kw]
__device__ unsigned g_cbits[(size_t)KW * NC];    // packed sign bits of class_hv, [kw][class]

// ---------------------------------------------------------------------------
// GEMM1: hv = x @ proj, fused sign epilogue -> hv_bin (fp32 +/-1) to d_out.
// fp32 SIMT tiled: BM=128, BN=128, BK=16, 256 threads, 8x8 per-thread tile.
// ---------------------------------------------------------------------------
__global__ __launch_bounds__(256) void gemm1_kernel(
    const float* __restrict__ A,     // x [MB, K1]
    const float* __restrict__ Bm,    // proj [K1, N1]
    float* __restrict__ hv_out)      // hv_bin [MB, N1]
{
    __shared__ float As[16][132];    // transposed A tile, padded (store conflicts ~2-way)
    __shared__ float Bs[16][128];

    const int tid = threadIdx.x;
    const int bx = blockIdx.x;       // N tile: 64 tiles
    const int by = blockIdx.y;       // M tile: 128 tiles
    const int tr = tid >> 4;         // 0..15
    const int tc = tid & 15;         // 0..15

    const int a_row  = tid >> 2;         // 0..63
    const int a_col  = (tid & 3) << 2;   // 0,4,8,12
    const int b_row  = tid >> 5;         // 0..7
    const int b_col  = (tid & 31) << 2;  // 0..124

    const float* Aptr = A + (size_t)by * 128 * K1;
    const float* Bptr = Bm + (size_t)bx * 128;

    float acc[8][8];
#pragma unroll
    for (int i = 0; i < 8; i++)
#pragma unroll
        for (int j = 0; j < 8; j++) acc[i][j] = 0.0f;

    for (int k0 = 0; k0 < K1; k0 += 16) {
        // Load A tile [128 rows x 16 k], transpose into As[k][m]
#pragma unroll
        for (int i = 0; i < 2; i++) {
            int r = a_row + i * 64;
            float4 v = *(const float4*)(Aptr + (size_t)r * K1 + k0 + a_col);
            As[a_col + 0][r] = v.x;
            As[a_col + 1][r] = v.y;
            As[a_col + 2][r] = v.z;
            As[a_col + 3][r] = v.w;
        }
        // Load B tile [16 k x 128 n]
#pragma unroll
        for (int i = 0; i < 2; i++) {
            int r = b_row + i * 8;
            *(float4*)(&Bs[r][b_col]) =
                *(const float4*)(Bptr + (size_t)(k0 + r) * N1 + b_col);
        }
        __syncthreads();

#pragma unroll
        for (int k = 0; k < 16; k++) {
            float a[8], b[8];
            *(float4*)&a[0] = *(const float4*)&As[k][tr * 8];
            *(float4*)&a[4] = *(const float4*)&As[k][tr * 8 + 4];
            *(float4*)&b[0] = *(const float4*)&Bs[k][tc * 8];
            *(float4*)&b[4] = *(const float4*)&Bs[k][tc * 8 + 4];
#pragma unroll
            for (int i = 0; i < 8; i++)
#pragma unroll
                for (int j = 0; j < 8; j++)
                    acc[i][j] = fmaf(a[i], b[j], acc[i][j]);
        }
        __syncthreads();
    }

    // Epilogue: sign binarize (hv >= 0 -> +1 else -1), vectorized stores
#pragma unroll
    for (int i = 0; i < 8; i++) {
        size_t row = (size_t)by * 128 + tr * 8 + i;
        float4 v0, v1;
        v0.x = (acc[i][0] >= 0.0f) ? 1.0f : -1.0f;
        v0.y = (acc[i][1] >= 0.0f) ? 1.0f : -1.0f;
        v0.z = (acc[i][2] >= 0.0f) ? 1.0f : -1.0f;
        v0.w = (acc[i][3] >= 0.0f) ? 1.0f : -1.0f;
        v1.x = (acc[i][4] >= 0.0f) ? 1.0f : -1.0f;
        v1.y = (acc[i][5] >= 0.0f) ? 1.0f : -1.0f;
        v1.z = (acc[i][6] >= 0.0f) ? 1.0f : -1.0f;
        v1.w = (acc[i][7] >= 0.0f) ? 1.0f : -1.0f;
        float* p = hv_out + row * N1 + (size_t)bx * 128 + tc * 8;
        *(float4*)(p)     = v0;
        *(float4*)(p + 4) = v1;
    }
}

// ---------------------------------------------------------------------------
// Pack hv_bin signs into bit words via warp ballot (coalesced 537MB read)
// ---------------------------------------------------------------------------
__global__ __launch_bounds__(256) void pack_rows_kernel(const float* __restrict__ hv)
{
    size_t i = (size_t)blockIdx.x * 256 + threadIdx.x;
    float v = hv[i];
    unsigned m = __ballot_sync(0xffffffffu, v > 0.0f);
    if ((threadIdx.x & 31) == 0) g_rbits[i >> 5] = m;
}

// ---------------------------------------------------------------------------
// Pack class_hv signs: g_cbits[kw][c], bit j of word kw <-> k = kw*32+j
// ---------------------------------------------------------------------------
__global__ __launch_bounds__(256) void pack_class_kernel(const float* __restrict__ chv)
{
    const int kw   = blockIdx.x;            // 0..255
    const int warp = threadIdx.x >> 5;      // 0..7
    const int lane = threadIdx.x & 31;

    for (int cg = warp; cg < 32; cg += 8) {
        int c = cg * 32 + lane;
        if (c < NC) {
            unsigned w = 0;
#pragma unroll
            for (int j = 0; j < 32; j++) {
                float v = chv[(size_t)(kw * 32 + j) * NC + c];
                w |= (v > 0.0f ? 1u : 0u) << j;
            }
            g_cbits[(size_t)kw * NC + c] = w;
        }
    }
}

// ---------------------------------------------------------------------------
// GEMM2 as xor/popcount: scores[b,c] = N1 - 2*popc(rbits[b] ^ cbits[c])
// Block: 64 rows x 64 classes; KT=32 kw per smem tile; 256 threads, 4x4/thread
// ---------------------------------------------------------------------------
__global__ __launch_bounds__(256) void scores_kernel(float* __restrict__ scores)
{
    __shared__ unsigned rs[64][33];   // [row][kw] padded
    __shared__ unsigned cs[32][64];   // [kw][class]

    const int tid = threadIdx.x;
    const int r0 = blockIdx.y * 64;
    const int c0 = blockIdx.x * 64;
    const int tr = tid >> 4;          // 0..15
    const int tc = tid & 15;          // 0..15

    int acc[4][4];
#pragma unroll
    for (int i = 0; i < 4; i++)
#pragma unroll
        for (int j = 0; j < 4; j++) acc[i][j] = 0;

    for (int t = 0; t < 8; t++) {
        const int kw0 = t * 32;
        // load row bits: 64 rows x 32 words
#pragma unroll
        for (int i = 0; i < 8; i++) {
            int idx = tid + i * 256;
            int rr = idx >> 5, jj = idx & 31;
            rs[rr][jj] = g_rbits[(size_t)(r0 + rr) * KW + kw0 + jj];
        }
        // load class bits: 32 words x 64 classes
#pragma unroll
        for (int i = 0; i < 8; i++) {
            int idx = tid + i * 256;
            int jj = idx >> 6, cc = idx & 63;
            int c = c0 + cc;
            cs[jj][cc] = (c < NC) ? g_cbits[(size_t)(kw0 + jj) * NC + c] : 0u;
        }
        __syncthreads();

#pragma unroll
        for (int j = 0; j < 32; j++) {
            unsigned rw[4], cw[4];
#pragma unroll
            for (int i = 0; i < 4; i++) rw[i] = rs[tr * 4 + i][j];
            uint4 cv = *(const uint4*)&cs[j][tc * 4];
            cw[0] = cv.x; cw[1] = cv.y; cw[2] = cv.z; cw[3] = cv.w;
#pragma unroll
            for (int i = 0; i < 4; i++)
#pragma unroll
                for (int ii = 0; ii < 4; ii++)
                    acc[i][ii] += __popc(rw[i] ^ cw[ii]);
        }
        __syncthreads();
    }

#pragma unroll
    for (int i = 0; i < 4; i++) {
        int r = r0 + tr * 4 + i;
#pragma unroll
        for (int ii = 0; ii < 4; ii++) {
            int c = c0 + tc * 4 + ii;
            if (c < NC)
                scores[(size_t)r * NC + c] = (float)(N1 - 2 * acc[i][ii]);
        }
    }
}

// ---------------------------------------------------------------------------
extern "C" void kernel_launch(void* const* d_in, const int* in_sizes, int n_in,
                              void* d_out, int out_size)
{
    const float* x    = (const float*)d_in[0];   // [16384, 2048]
    const float* proj = (const float*)d_in[1];   // [2048, 8192]
    const float* chv  = (const float*)d_in[2];   // [8192, 1000]

    float* scores = (float*)d_out;                       // [16384, 1000]
    float* hv     = scores + (size_t)MB * NC;            // [16384, 8192]

    dim3 g1(N1 / 128, MB / 128);                 // 64 x 128
    gemm1_kernel<<<g1, 256>>>(x, proj, hv);

    pack_rows_kernel<<<(unsigned)((size_t)MB * N1 / 256), 256>>>(hv);
    pack_class_kernel<<<KW, 256>>>(chv);

    dim3 gs(1024 / 64, MB / 64);                 // 16 x 256 (classes padded to 1024)
    scores_kernel<<<gs, 256>>>(scores);
}

// round 5
// speedup vs baseline: 2.1828x; 2.1828x over previous
#include <cuda_runtime.h>
#include <cuda_bf16.h>
#include <cstdint>

// Problem dims
#define MB   16384   // batch
#define K1   2048    // IN_DIM
#define N1   8192    // HV_DIM
#define NC   1000    // NUM_CLASSES
#define KW   256     // N1/32 packed words per row

// GEMM1 tile config (mma.sync path, BK=64 -> 128B SW128 rows)
#define BM   128
#define BN   256
#define BK   64
#define SM_A_OFF(sp) ((sp) * 16384)          // 2 limbs, each 128x64 bf16 = 16KB
#define SM_B_OFF     32768                   // B: 256x64 bf16 = 32KB
#define STAGE_BYTES  65536
#define SM_STAGE(s)  ((s) * STAGE_BYTES)
#define SMEM_TOTAL   (2 * STAGE_BYTES)       // 131072 bytes

#define TAU     0.08f                        // borderline threshold
#define WL_CAP  (1u << 22)                   // 4M worklist entries

// -------------------- device scratch (allocation-free rule) -----------------
__device__ __nv_bfloat16 g_xhi [(size_t)MB * K1];
__device__ __nv_bfloat16 g_xmid[(size_t)MB * K1];
__device__ __nv_bfloat16 g_projT[(size_t)N1 * K1];   // [N1, K1] K-major
__device__ unsigned g_rbits[(size_t)MB * KW];        // packed hv_bin signs
__device__ unsigned g_cbits[(size_t)KW * NC];        // packed class_hv signs
__device__ unsigned g_wl[WL_CAP];                    // borderline worklist
__device__ unsigned g_wl_count;

// -------------------- PTX helpers (baseline ISA only, sm_80+) ---------------
__device__ __forceinline__ uint32_t smem_u32(const void* p) {
    uint32_t a;
    asm("{ .reg .u64 t; cvta.to.shared.u64 t, %1; cvt.u32.u64 %0, t; }"
        : "=r"(a) : "l"(p));
    return a;
}
__device__ __forceinline__ void cp_async16(uint32_t dst, const void* src) {
    asm volatile("cp.async.cg.shared.global [%0], [%1], 16;\n"
                 :: "r"(dst), "l"(src) : "memory");
}
__device__ __forceinline__ void cp_commit() {
    asm volatile("cp.async.commit_group;" ::: "memory");
}
__device__ __forceinline__ void cp_wait1() {
    asm volatile("cp.async.wait_group 1;" ::: "memory");
}
__device__ __forceinline__ void cp_wait0() {
    asm volatile("cp.async.wait_group 0;" ::: "memory");
}
__device__ __forceinline__ void ldsm4(uint32_t& r0, uint32_t& r1, uint32_t& r2,
                                      uint32_t& r3, uint32_t addr) {
    asm volatile("ldmatrix.sync.aligned.m8n8.x4.shared.b16 {%0,%1,%2,%3}, [%4];"
                 : "=r"(r0), "=r"(r1), "=r"(r2), "=r"(r3) : "r"(addr));
}
__device__ __forceinline__ void mma_bf16(float* c, const uint32_t* a,
                                         const uint32_t* b) {
    asm volatile(
        "mma.sync.aligned.m16n8k16.row.col.f32.bf16.bf16.f32 "
        "{%0,%1,%2,%3}, {%4,%5,%6,%7}, {%8,%9}, {%0,%1,%2,%3};"
        : "+f"(c[0]), "+f"(c[1]), "+f"(c[2]), "+f"(c[3])
        : "r"(a[0]), "r"(a[1]), "r"(a[2]), "r"(a[3]), "r"(b[0]), "r"(b[1]));
}
// SW128: byte_off ^ ((byte_off>>3)&0x70), 16B-chunk granular
__device__ __forceinline__ uint32_t swz(uint32_t off) {
    return off ^ ((off >> 3) & 0x70);
}

// ---------------------------------------------------------------------------
__global__ void zero_count_kernel() { g_wl_count = 0; }

// ---------------------------------------------------------------------------
// prep: 2-way bf16 split of x (hi+mid captures 16 mantissa bits)
// ---------------------------------------------------------------------------
__global__ __launch_bounds__(256) void prep_split(const float* __restrict__ x)
{
    size_t i4 = ((size_t)blockIdx.x * 256 + threadIdx.x) * 4;
    float4 v = *(const float4*)(x + i4);
    const float f[4] = {v.x, v.y, v.z, v.w};
    __nv_bfloat16 h[4], m[4];
#pragma unroll
    for (int e = 0; e < 4; e++) {
        float a = f[e];
        __nv_bfloat16 hi = __float2bfloat16_rn(a);
        float r1 = a - __bfloat162float(hi);
        h[e] = hi; m[e] = __float2bfloat16_rn(r1);
    }
    ((__nv_bfloat162*)(g_xhi  + i4))[0] = __nv_bfloat162(h[0], h[1]);
    ((__nv_bfloat162*)(g_xhi  + i4))[1] = __nv_bfloat162(h[2], h[3]);
    ((__nv_bfloat162*)(g_xmid + i4))[0] = __nv_bfloat162(m[0], m[1]);
    ((__nv_bfloat162*)(g_xmid + i4))[1] = __nv_bfloat162(m[2], m[3]);
}

// ---------------------------------------------------------------------------
// prep: projT[n][k] = bf16(proj[k][n])  (exact, proj is +/-1)
// ---------------------------------------------------------------------------
__global__ __launch_bounds__(256) void prep_projT(const float* __restrict__ proj)
{
    __shared__ float t[32][33];
    const int n0 = blockIdx.x * 32, k0 = blockIdx.y * 32;
    const int tx = threadIdx.x, ty = threadIdx.y;   // (32, 8)
#pragma unroll
    for (int i = 0; i < 4; i++)
        t[ty + i * 8][tx] = proj[(size_t)(k0 + ty + i * 8) * N1 + n0 + tx];
    __syncthreads();
#pragma unroll
    for (int i = 0; i < 4; i++) {
        int r = ty + i * 8;
        g_projT[(size_t)(n0 + r) * K1 + k0 + tx] = __float2bfloat16_rn(t[tx][r]);
    }
}

// ---------------------------------------------------------------------------
// GEMM1 via mma.sync bf16 (2-limb split), sign epilogue + borderline flagging
// 128x256x64 CTA tile, 8 warps (2x4), 64x64 warp tiles, 2-stage cp.async.
// ---------------------------------------------------------------------------
__global__ __launch_bounds__(256, 1) void gemm1_mma(float* __restrict__ hv)
{
    extern __shared__ char smem[];
    const uint32_t sb = smem_u32(smem);
    const int tid = threadIdx.x, wid = tid >> 5, lane = tid & 31;
    const int warp_m = wid >> 2;        // 0..1  -> 64-row slab
    const int warp_n = wid & 3;         // 0..3  -> 64-col slab
    const int m0 = blockIdx.y * BM;
    const int n0 = blockIdx.x * BN;

    float c[4][8][4];
#pragma unroll
    for (int i = 0; i < 4; i++)
#pragma unroll
        for (int j = 0; j < 8; j++)
#pragma unroll
            for (int q = 0; q < 4; q++) c[i][j][q] = 0.0f;

    const __nv_bfloat16* const xs[2] = {g_xhi, g_xmid};

    auto load_stage = [&](int chunk, int s) {
        const size_t k0 = (size_t)chunk * BK;
#pragma unroll
        for (int sp = 0; sp < 2; sp++) {
            const char* base = (const char*)xs[sp] + ((size_t)m0 * K1 + k0) * 2;
#pragma unroll
            for (int i = 0; i < 4; i++) {
                int idx = tid + i * 256;            // 0..1023
                int r = idx >> 3, cc = idx & 7;
                uint32_t dst = sb + SM_STAGE(s) + SM_A_OFF(sp)
                             + swz((uint32_t)(r * 128 + cc * 16));
                cp_async16(dst, base + (size_t)r * (K1 * 2) + cc * 16);
            }
        }
        const char* bb = (const char*)g_projT + ((size_t)n0 * K1 + k0) * 2;
#pragma unroll
        for (int i = 0; i < 8; i++) {
            int idx = tid + i * 256;                // 0..2047
            int r = idx >> 3, cc = idx & 7;
            uint32_t dst = sb + SM_STAGE(s) + SM_B_OFF
                         + swz((uint32_t)(r * 128 + cc * 16));
            cp_async16(dst, bb + (size_t)r * (K1 * 2) + cc * 16);
        }
        cp_commit();
    };

    load_stage(0, 0);
    load_stage(1, 1);

    const int a_row = warp_m * 64 + (lane & 15);       // + mt*16
    const int a_kc  = (lane >> 4);                     // + ks*2
    const int b_row = warp_n * 64 + (lane & 7) + ((lane >> 4) << 3);  // + g*16
    const int b_kc  = (lane >> 3) & 1;                 // + ks*2

    for (int t = 0; t < 32; t++) {
        const int cur = t & 1;
        if (t == 31) cp_wait0(); else cp_wait1();
        __syncthreads();

        const uint32_t stg = sb + SM_STAGE(cur);
#pragma unroll
        for (int ks = 0; ks < 4; ks++) {
            uint32_t b[8][2];
#pragma unroll
            for (int g = 0; g < 4; g++) {
                uint32_t addr = stg + SM_B_OFF
                    + swz((uint32_t)((b_row + g * 16) * 128
                                     + (ks * 2 + b_kc) * 16));
                ldsm4(b[2 * g][0], b[2 * g][1], b[2 * g + 1][0], b[2 * g + 1][1],
                      addr);
            }
#pragma unroll
            for (int sp = 0; sp < 2; sp++) {
                uint32_t a[4][4];
#pragma unroll
                for (int mt = 0; mt < 4; mt++) {
                    uint32_t addr = stg + SM_A_OFF(sp)
                        + swz((uint32_t)((a_row + mt * 16) * 128
                                         + (ks * 2 + a_kc) * 16));
                    ldsm4(a[mt][0], a[mt][1], a[mt][2], a[mt][3], addr);
                }
#pragma unroll
                for (int mt = 0; mt < 4; mt++)
#pragma unroll
                    for (int nt = 0; nt < 8; nt++)
                        mma_bf16(c[mt][nt], a[mt], b[nt]);
            }
        }
        __syncthreads();
        if (t + 2 < 32) load_stage(t + 2, cur);
    }

    // ---- epilogue: sign -> +/-1 fp32 stores + borderline flagging ----
    const int er = m0 + warp_m * 64 + (lane >> 2);
    const int ec = n0 + warp_n * 64 + 2 * (lane & 3);

    unsigned nflag = 0;
    unsigned fl[16];                     // local flag buffer (rarely used)
#pragma unroll
    for (int mt = 0; mt < 4; mt++) {
#pragma unroll
        for (int nt = 0; nt < 8; nt++) {
            float2 v0, v1;
            v0.x = (c[mt][nt][0] >= 0.0f) ? 1.0f : -1.0f;
            v0.y = (c[mt][nt][1] >= 0.0f) ? 1.0f : -1.0f;
            v1.x = (c[mt][nt][2] >= 0.0f) ? 1.0f : -1.0f;
            v1.y = (c[mt][nt][3] >= 0.0f) ? 1.0f : -1.0f;
            const int r0r = er + mt * 16;
            const int cc  = ec + nt * 8;
            if (fabsf(c[mt][nt][0]) < TAU && nflag < 16)
                fl[nflag++] = ((unsigned)r0r << 13) | (unsigned)cc;
            if (fabsf(c[mt][nt][1]) < TAU && nflag < 16)
                fl[nflag++] = ((unsigned)r0r << 13) | (unsigned)(cc + 1);
            if (fabsf(c[mt][nt][2]) < TAU && nflag < 16)
                fl[nflag++] = ((unsigned)(r0r + 8) << 13) | (unsigned)cc;
            if (fabsf(c[mt][nt][3]) < TAU && nflag < 16)
                fl[nflag++] = ((unsigned)(r0r + 8) << 13) | (unsigned)(cc + 1);
            size_t o = (size_t)r0r * N1 + cc;
            *(float2*)(hv + o)          = v0;
            *(float2*)(hv + o + 8 * N1) = v1;
        }
    }

    // warp-aggregated worklist append
    unsigned any = __ballot_sync(0xffffffffu, nflag > 0);
    if (any) {
        unsigned off = nflag;
#pragma unroll
        for (int d = 1; d < 32; d <<= 1) {
            unsigned t2 = __shfl_up_sync(0xffffffffu, off, d);
            if (lane >= d) off += t2;
        }
        unsigned tot = __shfl_sync(0xffffffffu, off, 31);
        unsigned base = 0;
        if (lane == 31) base = atomicAdd(&g_wl_count, tot);
        base = __shfl_sync(0xffffffffu, base, 31);
        unsigned my = base + off - nflag;
        for (unsigned i = 0; i < nflag; i++)
            if (my + i < WL_CAP) g_wl[my + i] = fl[i];
    }
}

// ---------------------------------------------------------------------------
// Fixup: recompute borderline elements with the reference's exact rounding
// (single sequential ascending-k fp32 FMA chain).
// ---------------------------------------------------------------------------
__global__ __launch_bounds__(256) void fixup_kernel(const float* __restrict__ x,
                                                    float* __restrict__ hv)
{
    unsigned total = g_wl_count;
    if (total > WL_CAP) total = WL_CAP;
    for (unsigned i = blockIdx.x * 256 + threadIdx.x; i < total;
         i += gridDim.x * 256) {
        unsigned e = g_wl[i];
        int row = (int)(e >> 13);
        int col = (int)(e & 8191u);
        const float* xr = x + (size_t)row * K1;
        const __nv_bfloat16* pc = g_projT + (size_t)col * K1;
        float s = 0.0f;
        // strict sequential chain: rounding matches reference bitwise
        for (int k = 0; k < K1; k += 8) {
            float4 xa = *(const float4*)(xr + k);
            float4 xb = *(const float4*)(xr + k + 4);
            float p0 = __bfloat162float(pc[k + 0]);
            float p1 = __bfloat162float(pc[k + 1]);
            float p2 = __bfloat162float(pc[k + 2]);
            float p3 = __bfloat162float(pc[k + 3]);
            float p4 = __bfloat162float(pc[k + 4]);
            float p5 = __bfloat162float(pc[k + 5]);
            float p6 = __bfloat162float(pc[k + 6]);
            float p7 = __bfloat162float(pc[k + 7]);
            s = fmaf(xa.x, p0, s); s = fmaf(xa.y, p1, s);
            s = fmaf(xa.z, p2, s); s = fmaf(xa.w, p3, s);
            s = fmaf(xb.x, p4, s); s = fmaf(xb.y, p5, s);
            s = fmaf(xb.z, p6, s); s = fmaf(xb.w, p7, s);
        }
        hv[(size_t)row * N1 + col] = (s >= 0.0f) ? 1.0f : -1.0f;
    }
}

// ---------------------------------------------------------------------------
// Pack hv_bin signs into bit words via warp ballot (runs AFTER fixup)
// ---------------------------------------------------------------------------
__global__ __launch_bounds__(256) void pack_rows_kernel(const float* __restrict__ hv)
{
    size_t i = (size_t)blockIdx.x * 256 + threadIdx.x;
    float v = hv[i];
    unsigned m = __ballot_sync(0xffffffffu, v > 0.0f);
    if ((threadIdx.x & 31) == 0) g_rbits[i >> 5] = m;
}

// ---------------------------------------------------------------------------
// Pack class_hv signs
// ---------------------------------------------------------------------------
__global__ __launch_bounds__(256) void pack_class_kernel(const float* __restrict__ chv)
{
    const int kw   = blockIdx.x;            // 0..255
    const int warp = threadIdx.x >> 5;
    const int lane = threadIdx.x & 31;

    for (int cg = warp; cg < 32; cg += 8) {
        int c = cg * 32 + lane;
        if (c < NC) {
            unsigned w = 0;
#pragma unroll
            for (int j = 0; j < 32; j++) {
                float v = chv[(size_t)(kw * 32 + j) * NC + c];
                w |= (v > 0.0f ? 1u : 0u) << j;
            }
            g_cbits[(size_t)kw * NC + c] = w;
        }
    }
}

// ---------------------------------------------------------------------------
// GEMM2 as xor/popcount: scores[b,c] = N1 - 2*popc(rbits[b] ^ cbits[c])
// ---------------------------------------------------------------------------
__global__ __launch_bounds__(256) void scores_kernel(float* __restrict__ scores)
{
    __shared__ unsigned rs[64][33];
    __shared__ unsigned cs[32][64];

    const int tid = threadIdx.x;
    const int r0 = blockIdx.y * 64;
    const int c0 = blockIdx.x * 64;
    const int tr = tid >> 4;
    const int tc = tid & 15;

    int acc[4][4];
#pragma unroll
    for (int i = 0; i < 4; i++)
#pragma unroll
        for (int j = 0; j < 4; j++) acc[i][j] = 0;

    for (int t = 0; t < 8; t++) {
        const int kw0 = t * 32;
#pragma unroll
        for (int i = 0; i < 8; i++) {
            int idx = tid + i * 256;
            int rr = idx >> 5, jj = idx & 31;
            rs[rr][jj] = g_rbits[(size_t)(r0 + rr) * KW + kw0 + jj];
        }
#pragma unroll
        for (int i = 0; i < 8; i++) {
            int idx = tid + i * 256;
            int jj = idx >> 6, cc = idx & 63;
            int c = c0 + cc;
            cs[jj][cc] = (c < NC) ? g_cbits[(size_t)(kw0 + jj) * NC + c] : 0u;
        }
        __syncthreads();

#pragma unroll
        for (int j = 0; j < 32; j++) {
            unsigned rw[4], cw[4];
#pragma unroll
            for (int i = 0; i < 4; i++) rw[i] = rs[tr * 4 + i][j];
            uint4 cv = *(const uint4*)&cs[j][tc * 4];
            cw[0] = cv.x; cw[1] = cv.y; cw[2] = cv.z; cw[3] = cv.w;
#pragma unroll
            for (int i = 0; i < 4; i++)
#pragma unroll
                for (int ii = 0; ii < 4; ii++)
                    acc[i][ii] += __popc(rw[i] ^ cw[ii]);
        }
        __syncthreads();
    }

#pragma unroll
    for (int i = 0; i < 4; i++) {
        int r = r0 + tr * 4 + i;
#pragma unroll
        for (int ii = 0; ii < 4; ii++) {
            int c = c0 + tc * 4 + ii;
            if (c < NC)
                scores[(size_t)r * NC + c] = (float)(N1 - 2 * acc[i][ii]);
        }
    }
}

// ---------------------------------------------------------------------------
extern "C" void kernel_launch(void* const* d_in, const int* in_sizes, int n_in,
                              void* d_out, int out_size)
{
    const float* x    = (const float*)d_in[0];   // [16384, 2048]
    const float* proj = (const float*)d_in[1];   // [2048, 8192]
    const float* chv  = (const float*)d_in[2];   // [8192, 1000]

    float* scores = (float*)d_out;                       // [16384, 1000]
    float* hv     = scores + (size_t)MB * NC;            // [16384, 8192]

    cudaFuncSetAttribute(gemm1_mma, cudaFuncAttributeMaxDynamicSharedMemorySize,
                         SMEM_TOTAL);

    zero_count_kernel<<<1, 1>>>();
    prep_split<<<(unsigned)((size_t)MB * K1 / 1024), 256>>>(x);
    prep_projT<<<dim3(N1 / 32, K1 / 32), dim3(32, 8)>>>(proj);
    pack_class_kernel<<<KW, 256>>>(chv);

    gemm1_mma<<<dim3(N1 / BN, MB / BM), 256, SMEM_TOTAL>>>(hv);

    fixup_kernel<<<1024, 256>>>(x, hv);
    pack_rows_kernel<<<(unsigned)((size_t)MB * N1 / 256), 256>>>(hv);

    dim3 gs(1024 / 64, MB / 64);
    scores_kernel<<<gs, 256>>>(scores);
}

// round 8
// speedup vs baseline: 2.3477x; 1.0756x over previous
#include <cuda_runtime.h>
#include <cuda_bf16.h>
#include <cstdint>

// Problem dims
#define MB   16384   // batch
#define K1   2048    // IN_DIM
#define N1   8192    // HV_DIM
#define NC   1000    // NUM_CLASSES
#define NCP  1024    // padded classes

// GEMM tile config (mma.sync path, BK=64 -> 128B SW128 rows)
#define BM   128
#define BN   256
#define BK   64

// GEMM1 smem: 2 A-limbs (16KB each) + B (32KB) per stage
#define G1_A_OFF(sp) ((sp) * 16384)
#define G1_B_OFF     32768
#define G1_STAGE_BYTES  65536
#define G1_SMEM   (2 * G1_STAGE_BYTES)       // 131072

// GEMM2 smem: A (16KB) + B (32KB) per stage
#define G2_A_OFF     0
#define G2_B_OFF     16384
#define G2_STAGE_BYTES  49152
#define G2_SMEM   (2 * G2_STAGE_BYTES)       // 98304

#define TAU     0.08f                        // borderline threshold
#define WL_CAP  (1u << 22)                   // 4M worklist entries

// -------------------- device scratch (allocation-free rule) -----------------
__device__ __nv_bfloat16 g_xhi [(size_t)MB * K1];
__device__ __nv_bfloat16 g_xmid[(size_t)MB * K1];
__device__ __nv_bfloat16 g_projT[(size_t)N1 * K1];    // [N1, K1] K-major
__device__ __nv_bfloat16 g_hvb [(size_t)MB * N1];     // hv_bin as bf16
__device__ __nv_bfloat16 g_chvT[(size_t)NCP * N1];    // [NCP, N1] K-major, padded
__device__ unsigned g_wl[WL_CAP];                     // borderline worklist
__device__ unsigned g_wl_count;

// -------------------- PTX helpers (baseline ISA only, sm_80+) ---------------
__device__ __forceinline__ uint32_t smem_u32(const void* p) {
    uint32_t a;
    asm("{ .reg .u64 t; cvta.to.shared.u64 t, %1; cvt.u32.u64 %0, t; }"
        : "=r"(a) : "l"(p));
    return a;
}
__device__ __forceinline__ void cp_async16(uint32_t dst, const void* src) {
    asm volatile("cp.async.cg.shared.global [%0], [%1], 16;\n"
                 :: "r"(dst), "l"(src) : "memory");
}
__device__ __forceinline__ void cp_commit() {
    asm volatile("cp.async.commit_group;" ::: "memory");
}
__device__ __forceinline__ void cp_wait1() {
    asm volatile("cp.async.wait_group 1;" ::: "memory");
}
__device__ __forceinline__ void cp_wait0() {
    asm volatile("cp.async.wait_group 0;" ::: "memory");
}
__device__ __forceinline__ void ldsm4(uint32_t& r0, uint32_t& r1, uint32_t& r2,
                                      uint32_t& r3, uint32_t addr) {
    asm volatile("ldmatrix.sync.aligned.m8n8.x4.shared.b16 {%0,%1,%2,%3}, [%4];"
                 : "=r"(r0), "=r"(r1), "=r"(r2), "=r"(r3) : "r"(addr));
}
__device__ __forceinline__ void mma_bf16(float* c, const uint32_t* a,
                                         const uint32_t* b) {
    asm volatile(
        "mma.sync.aligned.m16n8k16.row.col.f32.bf16.bf16.f32 "
        "{%0,%1,%2,%3}, {%4,%5,%6,%7}, {%8,%9}, {%0,%1,%2,%3};"
        : "+f"(c[0]), "+f"(c[1]), "+f"(c[2]), "+f"(c[3])
        : "r"(a[0]), "r"(a[1]), "r"(a[2]), "r"(a[3]), "r"(b[0]), "r"(b[1]));
}
// SW128: byte_off ^ ((byte_off>>3)&0x70), 16B-chunk granular
__device__ __forceinline__ uint32_t swz(uint32_t off) {
    return off ^ ((off >> 3) & 0x70);
}

// ---------------------------------------------------------------------------
__global__ void zero_count_kernel() { g_wl_count = 0; }

// ---------------------------------------------------------------------------
// prep: 2-way bf16 split of x (hi+mid captures 16 mantissa bits)
// ---------------------------------------------------------------------------
__global__ __launch_bounds__(256) void prep_split(const float* __restrict__ x)
{
    size_t i4 = ((size_t)blockIdx.x * 256 + threadIdx.x) * 4;
    float4 v = *(const float4*)(x + i4);
    const float f[4] = {v.x, v.y, v.z, v.w};
    __nv_bfloat16 h[4], m[4];
#pragma unroll
    for (int e = 0; e < 4; e++) {
        float a = f[e];
        __nv_bfloat16 hi = __float2bfloat16_rn(a);
        float r1 = a - __bfloat162float(hi);
        h[e] = hi; m[e] = __float2bfloat16_rn(r1);
    }
    ((__nv_bfloat162*)(g_xhi  + i4))[0] = __nv_bfloat162(h[0], h[1]);
    ((__nv_bfloat162*)(g_xhi  + i4))[1] = __nv_bfloat162(h[2], h[3]);
    ((__nv_bfloat162*)(g_xmid + i4))[0] = __nv_bfloat162(m[0], m[1]);
    ((__nv_bfloat162*)(g_xmid + i4))[1] = __nv_bfloat162(m[2], m[3]);
}

// ---------------------------------------------------------------------------
// prep: projT[n][k] = bf16(proj[k][n])  (exact, proj is +/-1)
// ---------------------------------------------------------------------------
__global__ __launch_bounds__(256) void prep_projT(const float* __restrict__ proj)
{
    __shared__ float t[32][33];
    const int n0 = blockIdx.x * 32, k0 = blockIdx.y * 32;
    const int tx = threadIdx.x, ty = threadIdx.y;   // (32, 8)
#pragma unroll
    for (int i = 0; i < 4; i++)
        t[ty + i * 8][tx] = proj[(size_t)(k0 + ty + i * 8) * N1 + n0 + tx];
    __syncthreads();
#pragma unroll
    for (int i = 0; i < 4; i++) {
        int r = ty + i * 8;
        g_projT[(size_t)(n0 + r) * K1 + k0 + tx] = __float2bfloat16_rn(t[tx][r]);
    }
}

// ---------------------------------------------------------------------------
// prep: chvT[c][k] = bf16(class_hv[k][c]), zero-padded classes 1000..1023
// ---------------------------------------------------------------------------
__global__ __launch_bounds__(256) void prep_chvT(const float* __restrict__ chv)
{
    __shared__ float t[32][33];
    const int c0 = blockIdx.x * 32, k0 = blockIdx.y * 32;
    const int tx = threadIdx.x, ty = threadIdx.y;   // (32, 8)
#pragma unroll
    for (int i = 0; i < 4; i++) {
        int c = c0 + tx;
        t[ty + i * 8][tx] = (c < NC)
            ? chv[(size_t)(k0 + ty + i * 8) * NC + c] : 0.0f;
    }
    __syncthreads();
#pragma unroll
    for (int i = 0; i < 4; i++) {
        int r = ty + i * 8;     // class within tile
        g_chvT[(size_t)(c0 + r) * N1 + k0 + tx] = __float2bfloat16_rn(t[tx][r]);
    }
}

// ---------------------------------------------------------------------------
// GEMM1 via mma.sync bf16 (2-limb split), sign epilogue -> hv fp32 + hvb bf16
// + borderline flagging. 128x256x64 CTA tile, 8 warps, 2-stage cp.async.
// ---------------------------------------------------------------------------
__global__ __launch_bounds__(256, 1) void gemm1_mma(float* __restrict__ hv)
{
    extern __shared__ char smem[];
    const uint32_t sb = smem_u32(smem);
    const int tid = threadIdx.x, wid = tid >> 5, lane = tid & 31;
    const int warp_m = wid >> 2;
    const int warp_n = wid & 3;
    const int m0 = blockIdx.y * BM;
    const int n0 = blockIdx.x * BN;

    float c[4][8][4];
#pragma unroll
    for (int i = 0; i < 4; i++)
#pragma unroll
        for (int j = 0; j < 8; j++)
#pragma unroll
            for (int q = 0; q < 4; q++) c[i][j][q] = 0.0f;

    const __nv_bfloat16* const xs[2] = {g_xhi, g_xmid};

    auto load_stage = [&](int chunk, int s) {
        const size_t k0 = (size_t)chunk * BK;
#pragma unroll
        for (int sp = 0; sp < 2; sp++) {
            const char* base = (const char*)xs[sp] + ((size_t)m0 * K1 + k0) * 2;
#pragma unroll
            for (int i = 0; i < 4; i++) {
                int idx = tid + i * 256;
                int r = idx >> 3, cc = idx & 7;
                uint32_t dst = sb + s * G1_STAGE_BYTES + G1_A_OFF(sp)
                             + swz((uint32_t)(r * 128 + cc * 16));
                cp_async16(dst, base + (size_t)r * (K1 * 2) + cc * 16);
            }
        }
        const char* bb = (const char*)g_projT + ((size_t)n0 * K1 + k0) * 2;
#pragma unroll
        for (int i = 0; i < 8; i++) {
            int idx = tid + i * 256;
            int r = idx >> 3, cc = idx & 7;
            uint32_t dst = sb + s * G1_STAGE_BYTES + G1_B_OFF
                         + swz((uint32_t)(r * 128 + cc * 16));
            cp_async16(dst, bb + (size_t)r * (K1 * 2) + cc * 16);
        }
        cp_commit();
    };

    load_stage(0, 0);
    load_stage(1, 1);

    const int a_row = warp_m * 64 + (lane & 15);
    const int a_kc  = (lane >> 4);
    const int b_row = warp_n * 64 + (lane & 7) + ((lane >> 4) << 3);
    const int b_kc  = (lane >> 3) & 1;

    for (int t = 0; t < 32; t++) {
        const int cur = t & 1;
        if (t == 31) cp_wait0(); else cp_wait1();
        __syncthreads();

        const uint32_t stg = sb + cur * G1_STAGE_BYTES;
#pragma unroll
        for (int ks = 0; ks < 4; ks++) {
            uint32_t b[8][2];
#pragma unroll
            for (int g = 0; g < 4; g++) {
                uint32_t addr = stg + G1_B_OFF
                    + swz((uint32_t)((b_row + g * 16) * 128
                                     + (ks * 2 + b_kc) * 16));
                ldsm4(b[2 * g][0], b[2 * g][1], b[2 * g + 1][0], b[2 * g + 1][1],
                      addr);
            }
#pragma unroll
            for (int sp = 0; sp < 2; sp++) {
                uint32_t a[4][4];
#pragma unroll
                for (int mt = 0; mt < 4; mt++) {
                    uint32_t addr = stg + G1_A_OFF(sp)
                        + swz((uint32_t)((a_row + mt * 16) * 128
                                         + (ks * 2 + a_kc) * 16));
                    ldsm4(a[mt][0], a[mt][1], a[mt][2], a[mt][3], addr);
                }
#pragma unroll
                for (int mt = 0; mt < 4; mt++)
#pragma unroll
                    for (int nt = 0; nt < 8; nt++)
                        mma_bf16(c[mt][nt], a[mt], b[nt]);
            }
        }
        __syncthreads();
        if (t + 2 < 32) load_stage(t + 2, cur);
    }

    // ---- epilogue: sign -> fp32 hv + bf16 hvb + borderline flagging ----
    const int er = m0 + warp_m * 64 + (lane >> 2);
    const int ec = n0 + warp_n * 64 + 2 * (lane & 3);

    unsigned nflag = 0;
    unsigned fl[16];
    const __nv_bfloat16 pb = __float2bfloat16_rn(1.0f);
    const __nv_bfloat16 nb = __float2bfloat16_rn(-1.0f);
#pragma unroll
    for (int mt = 0; mt < 4; mt++) {
#pragma unroll
        for (int nt = 0; nt < 8; nt++) {
            bool s0 = c[mt][nt][0] >= 0.0f;
            bool s1 = c[mt][nt][1] >= 0.0f;
            bool s2 = c[mt][nt][2] >= 0.0f;
            bool s3 = c[mt][nt][3] >= 0.0f;
            float2 v0 = make_float2(s0 ? 1.0f : -1.0f, s1 ? 1.0f : -1.0f);
            float2 v1 = make_float2(s2 ? 1.0f : -1.0f, s3 ? 1.0f : -1.0f);
            const int r0r = er + mt * 16;
            const int cc  = ec + nt * 8;
            if (fabsf(c[mt][nt][0]) < TAU && nflag < 16)
                fl[nflag++] = ((unsigned)r0r << 13) | (unsigned)cc;
            if (fabsf(c[mt][nt][1]) < TAU && nflag < 16)
                fl[nflag++] = ((unsigned)r0r << 13) | (unsigned)(cc + 1);
            if (fabsf(c[mt][nt][2]) < TAU && nflag < 16)
                fl[nflag++] = ((unsigned)(r0r + 8) << 13) | (unsigned)cc;
            if (fabsf(c[mt][nt][3]) < TAU && nflag < 16)
                fl[nflag++] = ((unsigned)(r0r + 8) << 13) | (unsigned)(cc + 1);
            size_t o = (size_t)r0r * N1 + cc;
            *(float2*)(hv + o)          = v0;
            *(float2*)(hv + o + 8 * N1) = v1;
            *(__nv_bfloat162*)(g_hvb + o) =
                __nv_bfloat162(s0 ? pb : nb, s1 ? pb : nb);
            *(__nv_bfloat162*)(g_hvb + o + 8 * N1) =
                __nv_bfloat162(s2 ? pb : nb, s3 ? pb : nb);
        }
    }

    // warp-aggregated worklist append
    unsigned any = __ballot_sync(0xffffffffu, nflag > 0);
    if (any) {
        unsigned off = nflag;
#pragma unroll
        for (int d = 1; d < 32; d <<= 1) {
            unsigned t2 = __shfl_up_sync(0xffffffffu, off, d);
            if (lane >= d) off += t2;
        }
        unsigned tot = __shfl_sync(0xffffffffu, off, 31);
        unsigned base = 0;
        if (lane == 31) base = atomicAdd(&g_wl_count, tot);
        base = __shfl_sync(0xffffffffu, base, 31);
        unsigned my = base + off - nflag;
        for (unsigned i = 0; i < nflag; i++)
            if (my + i < WL_CAP) g_wl[my + i] = fl[i];
    }
}

// ---------------------------------------------------------------------------
// Fixup: recompute borderline elements with the reference's exact rounding
// (single sequential ascending-k fp32 FMA chain). Updates hv AND g_hvb.
// ---------------------------------------------------------------------------
__global__ __launch_bounds__(256) void fixup_kernel(const float* __restrict__ x,
                                                    float* __restrict__ hv)
{
    unsigned total = g_wl_count;
    if (total > WL_CAP) total = WL_CAP;
    for (unsigned i = blockIdx.x * 256 + threadIdx.x; i < total;
         i += gridDim.x * 256) {
        unsigned e = g_wl[i];
        int row = (int)(e >> 13);
        int col = (int)(e & 8191u);
        const float* xr = x + (size_t)row * K1;
        const __nv_bfloat16* pc = g_projT + (size_t)col * K1;
        float s = 0.0f;
        for (int k = 0; k < K1; k += 8) {
            float4 xa = *(const float4*)(xr + k);
            float4 xb = *(const float4*)(xr + k + 4);
            float p0 = __bfloat162float(pc[k + 0]);
            float p1 = __bfloat162float(pc[k + 1]);
            float p2 = __bfloat162float(pc[k + 2]);
            float p3 = __bfloat162float(pc[k + 3]);
            float p4 = __bfloat162float(pc[k + 4]);
            float p5 = __bfloat162float(pc[k + 5]);
            float p6 = __bfloat162float(pc[k + 6]);
            float p7 = __bfloat162float(pc[k + 7]);
            s = fmaf(xa.x, p0, s); s = fmaf(xa.y, p1, s);
            s = fmaf(xa.z, p2, s); s = fmaf(xa.w, p3, s);
            s = fmaf(xb.x, p4, s); s = fmaf(xb.y, p5, s);
            s = fmaf(xb.z, p6, s); s = fmaf(xb.w, p7, s);
        }
        float v = (s >= 0.0f) ? 1.0f : -1.0f;
        hv[(size_t)row * N1 + col] = v;
        g_hvb[(size_t)row * N1 + col] = __float2bfloat16_rn(v);
    }
}

// ---------------------------------------------------------------------------
// GEMM2 via mma.sync bf16: scores = hv_bin @ class_hv.
// Operands +/-1 (exact bf16); fp32 accumulation of integers |s|<=8192 is
// EXACT in any order. 128x256x64 tile, K=8192, 2-stage cp.async.
// ---------------------------------------------------------------------------
__global__ __launch_bounds__(256, 1) void gemm2_mma(float* __restrict__ scores)
{
    extern __shared__ char smem[];
    const uint32_t sb = smem_u32(smem);
    const int tid = threadIdx.x, wid = tid >> 5, lane = tid & 31;
    const int warp_m = wid >> 2;
    const int warp_n = wid & 3;
    const int m0 = blockIdx.y * BM;
    const int n0 = blockIdx.x * BN;

    float c[4][8][4];
#pragma unroll
    for (int i = 0; i < 4; i++)
#pragma unroll
        for (int j = 0; j < 8; j++)
#pragma unroll
            for (int q = 0; q < 4; q++) c[i][j][q] = 0.0f;

    auto load_stage = [&](int chunk, int s) {
        const size_t k0 = (size_t)chunk * BK;
        const char* ab = (const char*)g_hvb + ((size_t)m0 * N1 + k0) * 2;
#pragma unroll
        for (int i = 0; i < 4; i++) {
            int idx = tid + i * 256;
            int r = idx >> 3, cc = idx & 7;
            uint32_t dst = sb + s * G2_STAGE_BYTES + G2_A_OFF
                         + swz((uint32_t)(r * 128 + cc * 16));
            cp_async16(dst, ab + (size_t)r * (N1 * 2) + cc * 16);
        }
        const char* bb = (const char*)g_chvT + ((size_t)n0 * N1 + k0) * 2;
#pragma unroll
        for (int i = 0; i < 8; i++) {
            int idx = tid + i * 256;
            int r = idx >> 3, cc = idx & 7;
            uint32_t dst = sb + s * G2_STAGE_BYTES + G2_B_OFF
                         + swz((uint32_t)(r * 128 + cc * 16));
            cp_async16(dst, bb + (size_t)r * (N1 * 2) + cc * 16);
        }
        cp_commit();
    };

    load_stage(0, 0);
    load_stage(1, 1);

    const int a_row = warp_m * 64 + (lane & 15);
    const int a_kc  = (lane >> 4);
    const int b_row = warp_n * 64 + (lane & 7) + ((lane >> 4) << 3);
    const int b_kc  = (lane >> 3) & 1;

    const int NT = N1 / BK;   // 128 k-chunks
    for (int t = 0; t < NT; t++) {
        const int cur = t & 1;
        if (t == NT - 1) cp_wait0(); else cp_wait1();
        __syncthreads();

        const uint32_t stg = sb + cur * G2_STAGE_BYTES;
#pragma unroll
        for (int ks = 0; ks < 4; ks++) {
            uint32_t b[8][2];
#pragma unroll
            for (int g = 0; g < 4; g++) {
                uint32_t addr = stg + G2_B_OFF
                    + swz((uint32_t)((b_row + g * 16) * 128
                                     + (ks * 2 + b_kc) * 16));
                ldsm4(b[2 * g][0], b[2 * g][1], b[2 * g + 1][0], b[2 * g + 1][1],
                      addr);
            }
            uint32_t a[4][4];
#pragma unroll
            for (int mt = 0; mt < 4; mt++) {
                uint32_t addr = stg + G2_A_OFF
                    + swz((uint32_t)((a_row + mt * 16) * 128
                                     + (ks * 2 + a_kc) * 16));
                ldsm4(a[mt][0], a[mt][1], a[mt][2], a[mt][3], addr);
            }
#pragma unroll
            for (int mt = 0; mt < 4; mt++)
#pragma unroll
                for (int nt = 0; nt < 8; nt++)
                    mma_bf16(c[mt][nt], a[mt], b[nt]);
        }
        __syncthreads();
        if (t + 2 < NT) load_stage(t + 2, cur);
    }

    // ---- epilogue: store raw fp32 (exact integers), guard col < NC ----
    const int er = m0 + warp_m * 64 + (lane >> 2);
    const int ec = n0 + warp_n * 64 + 2 * (lane & 3);
#pragma unroll
    for (int mt = 0; mt < 4; mt++) {
#pragma unroll
        for (int nt = 0; nt < 8; nt++) {
            const int cc = ec + nt * 8;
            if (cc < NC) {
                const int r0r = er + mt * 16;
                *(float2*)(scores + (size_t)r0r * NC + cc) =
                    make_float2(c[mt][nt][0], c[mt][nt][1]);
                *(float2*)(scores + (size_t)(r0r + 8) * NC + cc) =
                    make_float2(c[mt][nt][2], c[mt][nt][3]);
            }
        }
    }
}

// ---------------------------------------------------------------------------
extern "C" void kernel_launch(void* const* d_in, const int* in_sizes, int n_in,
                              void* d_out, int out_size)
{
    const float* x    = (const float*)d_in[0];   // [16384, 2048]
    const float* proj = (const float*)d_in[1];   // [2048, 8192]
    const float* chv  = (const float*)d_in[2];   // [8192, 1000]

    float* scores = (float*)d_out;                       // [16384, 1000]
    float* hv     = scores + (size_t)MB * NC;            // [16384, 8192]

    cudaFuncSetAttribute(gemm1_mma, cudaFuncAttributeMaxDynamicSharedMemorySize,
                         G1_SMEM);
    cudaFuncSetAttribute(gemm2_mma, cudaFuncAttributeMaxDynamicSharedMemorySize,
                         G2_SMEM);

    zero_count_kernel<<<1, 1>>>();
    prep_split<<<(unsigned)((size_t)MB * K1 / 1024), 256>>>(x);
    prep_projT<<<dim3(N1 / 32, K1 / 32), dim3(32, 8)>>>(proj);
    prep_chvT<<<dim3(NCP / 32, N1 / 32), dim3(32, 8)>>>(chv);

    gemm1_mma<<<dim3(N1 / BN, MB / BM), 256, G1_SMEM>>>(hv);

    fixup_kernel<<<1024, 256>>>(x, hv);

    gemm2_mma<<<dim3(NCP / BN, MB / BM), 256, G2_SMEM>>>(scores);
}

// round 10
// speedup vs baseline: 2.3585x; 1.0046x over previous
#include <cuda_runtime.h>
#include <cuda_bf16.h>
#include <cstdint>

// Problem dims
#define MB   16384   // batch
#define K1   2048    // IN_DIM
#define N1   8192    // HV_DIM
#define NC   1000    // NUM_CLASSES
#define NCP  1024    // padded classes

// GEMM tile config (mma.sync path, BK=64 -> 128B SW128 rows)
#define BM   128
#define BN   256
#define BK   64

// GEMM1 smem: 2 A-limbs (16KB each) + B (32KB) per stage, 3 stages
#define G1_A_OFF(sp) ((sp) * 16384)
#define G1_B_OFF     32768
#define G1_STAGE_BYTES  65536
#define G1_SMEM   (3 * G1_STAGE_BYTES)       // 196608

// GEMM2 smem: A (16KB) + B (32KB) per stage, 3 stages
#define G2_A_OFF     0
#define G2_B_OFF     16384
#define G2_STAGE_BYTES  49152
#define G2_SMEM   (3 * G2_STAGE_BYTES)       // 147456

#define TAU     0.08f                        // borderline threshold
#define WL_CAP  (1u << 22)                   // 4M worklist entries

// -------------------- device scratch (allocation-free rule) -----------------
__device__ __nv_bfloat16 g_xhi [(size_t)MB * K1];
__device__ __nv_bfloat16 g_xmid[(size_t)MB * K1];
__device__ __nv_bfloat16 g_projT[(size_t)N1 * K1];    // [N1, K1] K-major
__device__ __nv_bfloat16 g_hvb [(size_t)MB * N1];     // hv_bin as bf16
__device__ __nv_bfloat16 g_chvT[(size_t)NCP * N1];    // [NCP, N1] K-major, padded
__device__ unsigned g_wl[WL_CAP];                     // borderline worklist
__device__ unsigned g_wl_count;

// -------------------- PTX helpers (baseline ISA only, sm_80+) ---------------
__device__ __forceinline__ uint32_t smem_u32(const void* p) {
    uint32_t a;
    asm("{ .reg .u64 t; cvta.to.shared.u64 t, %1; cvt.u32.u64 %0, t; }"
        : "=r"(a) : "l"(p));
    return a;
}
__device__ __forceinline__ void cp_async16(uint32_t dst, const void* src) {
    asm volatile("cp.async.cg.shared.global [%0], [%1], 16;\n"
                 :: "r"(dst), "l"(src) : "memory");
}
__device__ __forceinline__ void cp_commit() {
    asm volatile("cp.async.commit_group;" ::: "memory");
}
__device__ __forceinline__ void cp_wait1() {
    asm volatile("cp.async.wait_group 1;" ::: "memory");
}
__device__ __forceinline__ void cp_wait0() {
    asm volatile("cp.async.wait_group 0;" ::: "memory");
}
__device__ __forceinline__ void ldsm4(uint32_t& r0, uint32_t& r1, uint32_t& r2,
                                      uint32_t& r3, uint32_t addr) {
    asm volatile("ldmatrix.sync.aligned.m8n8.x4.shared.b16 {%0,%1,%2,%3}, [%4];"
                 : "=r"(r0), "=r"(r1), "=r"(r2), "=r"(r3) : "r"(addr));
}
__device__ __forceinline__ void mma_bf16(float* c, const uint32_t* a,
                                         const uint32_t* b) {
    asm volatile(
        "mma.sync.aligned.m16n8k16.row.col.f32.bf16.bf16.f32 "
        "{%0,%1,%2,%3}, {%4,%5,%6,%7}, {%8,%9}, {%0,%1,%2,%3};"
        : "+f"(c[0]), "+f"(c[1]), "+f"(c[2]), "+f"(c[3])
        : "r"(a[0]), "r"(a[1]), "r"(a[2]), "r"(a[3]), "r"(b[0]), "r"(b[1]));
}
// SW128: byte_off ^ ((byte_off>>3)&0x70), 16B-chunk granular
__device__ __forceinline__ uint32_t swz(uint32_t off) {
    return off ^ ((off >> 3) & 0x70);
}

// ---------------------------------------------------------------------------
__global__ void zero_count_kernel() { g_wl_count = 0; }

// ---------------------------------------------------------------------------
// prep: 2-way bf16 split of x (hi+mid captures 16 mantissa bits)
// ---------------------------------------------------------------------------
__global__ __launch_bounds__(256) void prep_split(const float* __restrict__ x)
{
    size_t i4 = ((size_t)blockIdx.x * 256 + threadIdx.x) * 4;
    float4 v = *(const float4*)(x + i4);
    const float f[4] = {v.x, v.y, v.z, v.w};
    __nv_bfloat16 h[4], m[4];
#pragma unroll
    for (int e = 0; e < 4; e++) {
        float a = f[e];
        __nv_bfloat16 hi = __float2bfloat16_rn(a);
        float r1 = a - __bfloat162float(hi);
        h[e] = hi; m[e] = __float2bfloat16_rn(r1);
    }
    ((__nv_bfloat162*)(g_xhi  + i4))[0] = __nv_bfloat162(h[0], h[1]);
    ((__nv_bfloat162*)(g_xhi  + i4))[1] = __nv_bfloat162(h[2], h[3]);
    ((__nv_bfloat162*)(g_xmid + i4))[0] = __nv_bfloat162(m[0], m[1]);
    ((__nv_bfloat162*)(g_xmid + i4))[1] = __nv_bfloat162(m[2], m[3]);
}

// ---------------------------------------------------------------------------
// prep: projT[n][k] = bf16(proj[k][n])  (exact, proj is +/-1)
// ---------------------------------------------------------------------------
__global__ __launch_bounds__(256) void prep_projT(const float* __restrict__ proj)
{
    __shared__ float t[32][33];
    const int n0 = blockIdx.x * 32, k0 = blockIdx.y * 32;
    const int tx = threadIdx.x, ty = threadIdx.y;   // (32, 8)
#pragma unroll
    for (int i = 0; i < 4; i++)
        t[ty + i * 8][tx] = proj[(size_t)(k0 + ty + i * 8) * N1 + n0 + tx];
    __syncthreads();
#pragma unroll
    for (int i = 0; i < 4; i++) {
        int r = ty + i * 8;
        g_projT[(size_t)(n0 + r) * K1 + k0 + tx] = __float2bfloat16_rn(t[tx][r]);
    }
}

// ---------------------------------------------------------------------------
// prep: chvT[c][k] = bf16(class_hv[k][c]), zero-padded classes 1000..1023
// ---------------------------------------------------------------------------
__global__ __launch_bounds__(256) void prep_chvT(const float* __restrict__ chv)
{
    __shared__ float t[32][33];
    const int c0 = blockIdx.x * 32, k0 = blockIdx.y * 32;
    const int tx = threadIdx.x, ty = threadIdx.y;   // (32, 8)
#pragma unroll
    for (int i = 0; i < 4; i++) {
        int c = c0 + tx;
        t[ty + i * 8][tx] = (c < NC)
            ? chv[(size_t)(k0 + ty + i * 8) * NC + c] : 0.0f;
    }
    __syncthreads();
#pragma unroll
    for (int i = 0; i < 4; i++) {
        int r = ty + i * 8;     // class within tile
        g_chvT[(size_t)(c0 + r) * N1 + k0 + tx] = __float2bfloat16_rn(t[tx][r]);
    }
}

// ---------------------------------------------------------------------------
// GEMM1 via mma.sync bf16 (2-limb split), sign epilogue -> hv fp32 + hvb bf16
// + borderline flagging. 128x256x64 CTA tile, 8 warps, 3-stage cp.async.
// ---------------------------------------------------------------------------
__global__ __launch_bounds__(256, 1) void gemm1_mma(float* __restrict__ hv)
{
    extern __shared__ char smem[];
    const uint32_t sb = smem_u32(smem);
    const int tid = threadIdx.x, wid = tid >> 5, lane = tid & 31;
    const int warp_m = wid >> 2;
    const int warp_n = wid & 3;
    const int m0 = blockIdx.y * BM;
    const int n0 = blockIdx.x * BN;

    float c[4][8][4];
#pragma unroll
    for (int i = 0; i < 4; i++)
#pragma unroll
        for (int j = 0; j < 8; j++)
#pragma unroll
            for (int q = 0; q < 4; q++) c[i][j][q] = 0.0f;

    const __nv_bfloat16* const xs[2] = {g_xhi, g_xmid};

    auto load_stage = [&](int chunk, int s) {
        const size_t k0 = (size_t)chunk * BK;
#pragma unroll
        for (int sp = 0; sp < 2; sp++) {
            const char* base = (const char*)xs[sp] + ((size_t)m0 * K1 + k0) * 2;
#pragma unroll
            for (int i = 0; i < 4; i++) {
                int idx = tid + i * 256;
                int r = idx >> 3, cc = idx & 7;
                uint32_t dst = sb + s * G1_STAGE_BYTES + G1_A_OFF(sp)
                             + swz((uint32_t)(r * 128 + cc * 16));
                cp_async16(dst, base + (size_t)r * (K1 * 2) + cc * 16);
            }
        }
        const char* bb = (const char*)g_projT + ((size_t)n0 * K1 + k0) * 2;
#pragma unroll
        for (int i = 0; i < 8; i++) {
            int idx = tid + i * 256;
            int r = idx >> 3, cc = idx & 7;
            uint32_t dst = sb + s * G1_STAGE_BYTES + G1_B_OFF
                         + swz((uint32_t)(r * 128 + cc * 16));
            cp_async16(dst, bb + (size_t)r * (K1 * 2) + cc * 16);
        }
        cp_commit();
    };

    load_stage(0, 0);
    load_stage(1, 1);

    const int a_row = warp_m * 64 + (lane & 15);
    const int a_kc  = (lane >> 4);
    const int b_row = warp_n * 64 + (lane & 7) + ((lane >> 4) << 3);
    const int b_kc  = (lane >> 3) & 1;

    int sidx = 0;                         // buffer holding chunk t
    for (int t = 0; t < 32; t++) {
        if (t == 31) cp_wait0(); else cp_wait1();
        __syncthreads();                  // single barrier per chunk

        // issue loads for t+2 into the buffer last read at t-1 (free now)
        if (t + 2 < 32) {
            int s2 = sidx + 2; if (s2 >= 3) s2 -= 3;
            load_stage(t + 2, s2);
        }

        const uint32_t stg = sb + sidx * G1_STAGE_BYTES;
#pragma unroll
        for (int ks = 0; ks < 4; ks++) {
            uint32_t b[8][2];
#pragma unroll
            for (int g = 0; g < 4; g++) {
                uint32_t addr = stg + G1_B_OFF
                    + swz((uint32_t)((b_row + g * 16) * 128
                                     + (ks * 2 + b_kc) * 16));
                ldsm4(b[2 * g][0], b[2 * g][1], b[2 * g + 1][0], b[2 * g + 1][1],
                      addr);
            }
#pragma unroll
            for (int sp = 0; sp < 2; sp++) {
                uint32_t a[4][4];
#pragma unroll
                for (int mt = 0; mt < 4; mt++) {
                    uint32_t addr = stg + G1_A_OFF(sp)
                        + swz((uint32_t)((a_row + mt * 16) * 128
                                         + (ks * 2 + a_kc) * 16));
                    ldsm4(a[mt][0], a[mt][1], a[mt][2], a[mt][3], addr);
                }
#pragma unroll
                for (int mt = 0; mt < 4; mt++)
#pragma unroll
                    for (int nt = 0; nt < 8; nt++)
                        mma_bf16(c[mt][nt], a[mt], b[nt]);
            }
        }
        sidx = sidx + 1; if (sidx >= 3) sidx -= 3;
    }

    // ---- epilogue: sign -> fp32 hv + bf16 hvb + borderline flagging ----
    const int er = m0 + warp_m * 64 + (lane >> 2);
    const int ec = n0 + warp_n * 64 + 2 * (lane & 3);

    unsigned nflag = 0;
    unsigned fl[16];
    const __nv_bfloat16 pb = __float2bfloat16_rn(1.0f);
    const __nv_bfloat16 nb = __float2bfloat16_rn(-1.0f);
#pragma unroll
    for (int mt = 0; mt < 4; mt++) {
#pragma unroll
        for (int nt = 0; nt < 8; nt++) {
            bool s0 = c[mt][nt][0] >= 0.0f;
            bool s1 = c[mt][nt][1] >= 0.0f;
            bool s2 = c[mt][nt][2] >= 0.0f;
            bool s3 = c[mt][nt][3] >= 0.0f;
            float2 v0 = make_float2(s0 ? 1.0f : -1.0f, s1 ? 1.0f : -1.0f);
            float2 v1 = make_float2(s2 ? 1.0f : -1.0f, s3 ? 1.0f : -1.0f);
            const int r0r = er + mt * 16;
            const int cc  = ec + nt * 8;
            if (fabsf(c[mt][nt][0]) < TAU && nflag < 16)
                fl[nflag++] = ((unsigned)r0r << 13) | (unsigned)cc;
            if (fabsf(c[mt][nt][1]) < TAU && nflag < 16)
                fl[nflag++] = ((unsigned)r0r << 13) | (unsigned)(cc + 1);
            if (fabsf(c[mt][nt][2]) < TAU && nflag < 16)
                fl[nflag++] = ((unsigned)(r0r + 8) << 13) | (unsigned)cc;
            if (fabsf(c[mt][nt][3]) < TAU && nflag < 16)
                fl[nflag++] = ((unsigned)(r0r + 8) << 13) | (unsigned)(cc + 1);
            size_t o = (size_t)r0r * N1 + cc;
            *(float2*)(hv + o)          = v0;
            *(float2*)(hv + o + 8 * N1) = v1;
            *(__nv_bfloat162*)(g_hvb + o) =
                __nv_bfloat162(s0 ? pb : nb, s1 ? pb : nb);
            *(__nv_bfloat162*)(g_hvb + o + 8 * N1) =
                __nv_bfloat162(s2 ? pb : nb, s3 ? pb : nb);
        }
    }

    // warp-aggregated worklist append
    unsigned any = __ballot_sync(0xffffffffu, nflag > 0);
    if (any) {
        unsigned off = nflag;
#pragma unroll
        for (int d = 1; d < 32; d <<= 1) {
            unsigned t2 = __shfl_up_sync(0xffffffffu, off, d);
            if (lane >= d) off += t2;
        }
        unsigned tot = __shfl_sync(0xffffffffu, off, 31);
        unsigned base = 0;
        if (lane == 31) base = atomicAdd(&g_wl_count, tot);
        base = __shfl_sync(0xffffffffu, base, 31);
        unsigned my = base + off - nflag;
        for (unsigned i = 0; i < nflag; i++)
            if (my + i < WL_CAP) g_wl[my + i] = fl[i];
    }
}

// ---------------------------------------------------------------------------
// Fixup: recompute borderline elements with the reference's exact rounding
// (single sequential ascending-k fp32 FMA chain). Updates hv AND g_hvb.
// ---------------------------------------------------------------------------
__global__ __launch_bounds__(256) void fixup_kernel(const float* __restrict__ x,
                                                    float* __restrict__ hv)
{
    unsigned total = g_wl_count;
    if (total > WL_CAP) total = WL_CAP;
    for (unsigned i = blockIdx.x * 256 + threadIdx.x; i < total;
         i += gridDim.x * 256) {
        unsigned e = g_wl[i];
        int row = (int)(e >> 13);
        int col = (int)(e & 8191u);
        const float* xr = x + (size_t)row * K1;
        const __nv_bfloat16* pc = g_projT + (size_t)col * K1;
        float s = 0.0f;
        for (int k = 0; k < K1; k += 8) {
            float4 xa = *(const float4*)(xr + k);
            float4 xb = *(const float4*)(xr + k + 4);
            float p0 = __bfloat162float(pc[k + 0]);
            float p1 = __bfloat162float(pc[k + 1]);
            float p2 = __bfloat162float(pc[k + 2]);
            float p3 = __bfloat162float(pc[k + 3]);
            float p4 = __bfloat162float(pc[k + 4]);
            float p5 = __bfloat162float(pc[k + 5]);
            float p6 = __bfloat162float(pc[k + 6]);
            float p7 = __bfloat162float(pc[k + 7]);
            s = fmaf(xa.x, p0, s); s = fmaf(xa.y, p1, s);
            s = fmaf(xa.z, p2, s); s = fmaf(xa.w, p3, s);
            s = fmaf(xb.x, p4, s); s = fmaf(xb.y, p5, s);
            s = fmaf(xb.z, p6, s); s = fmaf(xb.w, p7, s);
        }
        float v = (s >= 0.0f) ? 1.0f : -1.0f;
        hv[(size_t)row * N1 + col] = v;
        g_hvb[(size_t)row * N1 + col] = __float2bfloat16_rn(v);
    }
}

// ---------------------------------------------------------------------------
// GEMM2 via mma.sync bf16: scores = hv_bin @ class_hv.
// Operands +/-1 (exact bf16); fp32 accumulation of integers |s|<=8192 is
// EXACT in any order. 128x256x64 tile, K=8192, 3-stage cp.async.
// ---------------------------------------------------------------------------
__global__ __launch_bounds__(256, 1) void gemm2_mma(float* __restrict__ scores)
{
    extern __shared__ char smem[];
    const uint32_t sb = smem_u32(smem);
    const int tid = threadIdx.x, wid = tid >> 5, lane = tid & 31;
    const int warp_m = wid >> 2;
    const int warp_n = wid & 3;
    const int m0 = blockIdx.y * BM;
    const int n0 = blockIdx.x * BN;

    float c[4][8][4];
#pragma unroll
    for (int i = 0; i < 4; i++)
#pragma unroll
        for (int j = 0; j < 8; j++)
#pragma unroll
            for (int q = 0; q < 4; q++) c[i][j][q] = 0.0f;

    auto load_stage = [&](int chunk, int s) {
        const size_t k0 = (size_t)chunk * BK;
        const char* ab = (const char*)g_hvb + ((size_t)m0 * N1 + k0) * 2;
#pragma unroll
        for (int i = 0; i < 4; i++) {
            int idx = tid + i * 256;
            int r = idx >> 3, cc = idx & 7;
            uint32_t dst = sb + s * G2_STAGE_BYTES + G2_A_OFF
                         + swz((uint32_t)(r * 128 + cc * 16));
            cp_async16(dst, ab + (size_t)r * (N1 * 2) + cc * 16);
        }
        const char* bb = (const char*)g_chvT + ((size_t)n0 * N1 + k0) * 2;
#pragma unroll
        for (int i = 0; i < 8; i++) {
            int idx = tid + i * 256;
            int r = idx >> 3, cc = idx & 7;
            uint32_t dst = sb + s * G2_STAGE_BYTES + G2_B_OFF
                         + swz((uint32_t)(r * 128 + cc * 16));
            cp_async16(dst, bb + (size_t)r * (N1 * 2) + cc * 16);
        }
        cp_commit();
    };

    load_stage(0, 0);
    load_stage(1, 1);

    const int a_row = warp_m * 64 + (lane & 15);
    const int a_kc  = (lane >> 4);
    const int b_row = warp_n * 64 + (lane & 7) + ((lane >> 4) << 3);
    const int b_kc  = (lane >> 3) & 1;

    const int NT = N1 / BK;   // 128 k-chunks
    int sidx = 0;
    for (int t = 0; t < NT; t++) {
        if (t == NT - 1) cp_wait0(); else cp_wait1();
        __syncthreads();

        if (t + 2 < NT) {
            int s2 = sidx + 2; if (s2 >= 3) s2 -= 3;
            load_stage(t + 2, s2);
        }

        const uint32_t stg = sb + sidx * G2_STAGE_BYTES;
#pragma unroll
        for (int ks = 0; ks < 4; ks++) {
            uint32_t b[8][2];
#pragma unroll
            for (int g = 0; g < 4; g++) {
                uint32_t addr = stg + G2_B_OFF
                    + swz((uint32_t)((b_row + g * 16) * 128
                                     + (ks * 2 + b_kc) * 16));
                ldsm4(b[2 * g][0], b[2 * g][1], b[2 * g + 1][0], b[2 * g + 1][1],
                      addr);
            }
            uint32_t a[4][4];
#pragma unroll
            for (int mt = 0; mt < 4; mt++) {
                uint32_t addr = stg + G2_A_OFF
                    + swz((uint32_t)((a_row + mt * 16) * 128
                                     + (ks * 2 + a_kc) * 16));
                ldsm4(a[mt][0], a[mt][1], a[mt][2], a[mt][3], addr);
            }
#pragma unroll
            for (int mt = 0; mt < 4; mt++)
#pragma unroll
                for (int nt = 0; nt < 8; nt++)
                    mma_bf16(c[mt][nt], a[mt], b[nt]);
        }
        sidx = sidx + 1; if (sidx >= 3) sidx -= 3;
    }

    // ---- epilogue: store raw fp32 (exact integers), guard col < NC ----
    const int er = m0 + warp_m * 64 + (lane >> 2);
    const int ec = n0 + warp_n * 64 + 2 * (lane & 3);
#pragma unroll
    for (int mt = 0; mt < 4; mt++) {
#pragma unroll
        for (int nt = 0; nt < 8; nt++) {
            const int cc = ec + nt * 8;
            if (cc < NC) {
                const int r0r = er + mt * 16;
                *(float2*)(scores + (size_t)r0r * NC + cc) =
                    make_float2(c[mt][nt][0], c[mt][nt][1]);
                *(float2*)(scores + (size_t)(r0r + 8) * NC + cc) =
                    make_float2(c[mt][nt][2], c[mt][nt][3]);
            }
        }
    }
}

// ---------------------------------------------------------------------------
extern "C" void kernel_launch(void* const* d_in, const int* in_sizes, int n_in,
                              void* d_out, int out_size)
{
    const float* x    = (const float*)d_in[0];   // [16384, 2048]
    const float* proj = (const float*)d_in[1];   // [2048, 8192]
    const float* chv  = (const float*)d_in[2];   // [8192, 1000]

    float* scores = (float*)d_out;                       // [16384, 1000]
    float* hv     = scores + (size_t)MB * NC;            // [16384, 8192]

    cudaFuncSetAttribute(gemm1_mma, cudaFuncAttributeMaxDynamicSharedMemorySize,
                         G1_SMEM);
    cudaFuncSetAttribute(gemm2_mma, cudaFuncAttributeMaxDynamicSharedMemorySize,
                         G2_SMEM);

    zero_count_kernel<<<1, 1>>>();
    prep_split<<<(unsigned)((size_t)MB * K1 / 1024), 256>>>(x);
    prep_projT<<<dim3(N1 / 32, K1 / 32), dim3(32, 8)>>>(proj);
    prep_chvT<<<dim3(NCP / 32, N1 / 32), dim3(32, 8)>>>(chv);

    gemm1_mma<<<dim3(N1 / BN, MB / BM), 256, G1_SMEM>>>(hv);

    fixup_kernel<<<1024, 256>>>(x, hv);

    gemm2_mma<<<dim3(NCP / BN, MB / BM), 256, G2_SMEM>>>(scores);
}